// round 5
// baseline (speedup 1.0000x reference)
#include <cuda_runtime.h>
#include <cuda_bf16.h>
#include <cstdint>

// Problem constants
#define E_  8
#define H_  1024
#define F_  4096
#define T_  16384
#define TPE 2048   // tokens per expert

// ---------------- device scratch (static, allocation-free) ----------------
__device__ float g_xr  [(size_t)T_ * H_];        //  64 MB, RNA-rounded X
__device__ float g_w1t [(size_t)E_ * F_ * H_];   // 128 MB, W1^T per expert [E,F,H]
__device__ float g_w2t [(size_t)E_ * H_ * F_];   // 128 MB, W2^T per expert [E,H,F]
__device__ float g_inter[(size_t)E_ * TPE * F_]; // 256 MB, gelu(X@W1), tf32-rounded

// ---------------- helpers ----------------
__device__ __forceinline__ float tf32r(float x) {
    uint32_t u;
    asm("cvt.rna.tf32.f32 %0, %1;" : "=r"(u) : "f"(x));
    return __uint_as_float(u);
}

#define SMEM_SWZ(off) ((off) ^ (((off) >> 3) & 0x70))

__device__ __forceinline__ void cp_async16(uint32_t sm, const void* g) {
    asm volatile("cp.async.cg.shared.global [%0], [%1], 16;" :: "r"(sm), "l"(g));
}
#define CP_COMMIT()   asm volatile("cp.async.commit_group;" ::: "memory")
#define CP_WAIT_1()   asm volatile("cp.async.wait_group 1;" ::: "memory")
#define CP_WAIT_0()   asm volatile("cp.async.wait_group 0;" ::: "memory")

__device__ __forceinline__ uint32_t smem_u32(const void* p) {
    uint32_t a;
    asm("{ .reg .u64 t; cvta.to.shared.u64 t, %1; cvt.u32.u64 %0, t; }" : "=r"(a) : "l"(p));
    return a;
}

__device__ __forceinline__ float lds_f32(uint32_t addr) {
    float v;
    asm volatile("ld.shared.f32 %0, [%1];" : "=f"(v) : "r"(addr));
    return v;
}

// mma.sync m16n8k8 tf32 (portable PTX, lowers to legacy HMMA on sm_103)
__device__ __forceinline__ void mma_tf32(float* d,
                                         uint32_t a0, uint32_t a1, uint32_t a2, uint32_t a3,
                                         uint32_t b0, uint32_t b1) {
    asm volatile(
        "mma.sync.aligned.m16n8k8.row.col.f32.tf32.tf32.f32 "
        "{%0,%1,%2,%3}, {%4,%5,%6,%7}, {%8,%9}, {%0,%1,%2,%3};"
        : "+f"(d[0]), "+f"(d[1]), "+f"(d[2]), "+f"(d[3])
        : "r"(a0), "r"(a1), "r"(a2), "r"(a3), "r"(b0), "r"(b1));
}

__device__ __forceinline__ float gelu_tanh(float x) {
    float u = 0.7978845608028654f * (x + 0.044715f * x * x * x);
    float au = fabsf(u);
    float e = __expf(-2.0f * au);
    float t = (1.0f - e) * __frcp_rn(1.0f + e);
    t = copysignf(t, u);
    return 0.5f * x * (1.0f + t);
}

// ---------------- prep kernels ----------------
__global__ void round_x_kernel(const float4* __restrict__ x, float4* __restrict__ o, int n4) {
    int i = blockIdx.x * blockDim.x + threadIdx.x;
    if (i < n4) {
        float4 v = x[i];
        v.x = tf32r(v.x); v.y = tf32r(v.y); v.z = tf32r(v.z); v.w = tf32r(v.w);
        o[i] = v;
    }
}

// W [E][R][C] -> WT [E][C][R], fused RNA rounding. block (32,8), grid (C/32, R/32, E)
__global__ void transpose_rna_kernel(const float* __restrict__ W, float* __restrict__ WT,
                                     int R, int C) {
    __shared__ float t[32][33];
    int e = blockIdx.z;
    const float* Wb = W + (size_t)e * R * C;
    float* Tb = WT + (size_t)e * R * C;
    int c0 = blockIdx.x * 32, r0 = blockIdx.y * 32;
    int tx = threadIdx.x, ty = threadIdx.y;
#pragma unroll
    for (int i = 0; i < 32; i += 8)
        t[ty + i][tx] = tf32r(Wb[(size_t)(r0 + ty + i) * C + c0 + tx]);
    __syncthreads();
#pragma unroll
    for (int i = 0; i < 32; i += 8)
        Tb[(size_t)(c0 + ty + i) * R + r0 + tx] = t[tx][ty + i];
}

// ---------------- mma.sync tf32 GEMM: C[M,N] = A(K-major) . B(K-major)^T ----------------
// CTA tile 128x128, 256 threads, warp grid 2(m) x 4(n), warp tile 64x32.
// 3 stages x 32KB = 96KB smem; with 128 regs/thread this still co-schedules
// 2 CTAs/SM (2x96KB <= 228KB, 2x32K regs = 64K). Single barrier per k-slab,
// depth-2 cp.async prefetch.
#define STAGES      3
#define STAGE_BYTES 32768            // 16KB A + 16KB B per 32-K slab
#define GEMM_SMEM   (STAGES * STAGE_BYTES)

template <bool GELU>
__global__ __launch_bounds__(256, 2) void gemm_mma_kernel(
    const float* __restrict__ A, const float* __restrict__ B, float* __restrict__ C,
    int lda, int ldb, int ldc,
    long sAe, long sBe, long sCe, int KT)
{
    extern __shared__ char smem[];
    uint32_t sb = smem_u32(smem);
    int tid = threadIdx.x;
    int lane = tid & 31, wid = tid >> 5;
    int g = lane >> 2, tig = lane & 3;
    int wm = wid & 1, wn = wid >> 1;
    int nt = blockIdx.x, mt = blockIdx.y, e = blockIdx.z;

    const float* Abase = A + (long)e * sAe + (long)mt * 128 * lda;
    const float* Bbase = B + (long)e * sBe + (long)nt * 128 * ldb;

    // per-stage loader: 128 rows x 128B per operand, SW128 swizzle, 16B chunks
    auto load_stage = [&](int stg, int kt) {
        uint32_t sA = sb + stg * STAGE_BYTES;
        uint32_t sB = sA + 16384;
        const float* ga = Abase + kt * 32;
        const float* gb = Bbase + kt * 32;
#pragma unroll
        for (int i = 0; i < 4; i++) {
            int id = tid + i * 256;
            int row = id >> 3;
            int c = (id & 7) * 16;
            cp_async16(sA + SMEM_SWZ(row * 128 + c), (const char*)(ga + (long)row * lda) + c);
        }
#pragma unroll
        for (int i = 0; i < 4; i++) {
            int id = tid + i * 256;
            int row = id >> 3;
            int c = (id & 7) * 16;
            cp_async16(sB + SMEM_SWZ(row * 128 + c), (const char*)(gb + (long)row * ldb) + c);
        }
    };

    // fragment row addressing (byte base within stage + XOR key for SW128)
    uint32_t aOff[8], aKey[8];   // [m-atom*2 + half]
#pragma unroll
    for (int i = 0; i < 4; i++)
#pragma unroll
        for (int h = 0; h < 2; h++) {
            int row = wm * 64 + i * 16 + h * 8 + g;
            aOff[i * 2 + h] = (uint32_t)(row * 128);
            aKey[i * 2 + h] = (uint32_t)((row & 7) << 4);
        }
    uint32_t bOff[4], bKey[4];   // [n-atom]
#pragma unroll
    for (int nn = 0; nn < 4; nn++) {
        int row = wn * 32 + nn * 8 + g;
        bOff[nn] = (uint32_t)(16384 + row * 128);
        bKey[nn] = (uint32_t)((row & 7) << 4);
    }

    float acc[4][4][4];
#pragma unroll
    for (int i = 0; i < 4; i++)
#pragma unroll
        for (int nn = 0; nn < 4; nn++)
#pragma unroll
            for (int r = 0; r < 4; r++) acc[i][nn][r] = 0.0f;

    // prologue: 2 slabs in flight
    load_stage(0, 0); CP_COMMIT();
    load_stage(1, 1); CP_COMMIT();

    // stage index tracker (avoids % in the loop)
    int cur = 0, nxs = 2;
    for (int kt = 0; kt < KT; kt++) {
        // slab kt must be resident; keep at most the kt+1 group pending
        if (kt < KT - 1) { CP_WAIT_1(); } else { CP_WAIT_0(); }
        // single barrier: also proves every warp finished reading buffer `nxs`
        // (it was consumed at iteration kt-1), so we can overwrite it below.
        __syncthreads();

        int nx = kt + 2;
        if (nx < KT) {
            load_stage(nxs, nx);
            CP_COMMIT();
        }

        uint32_t stg = sb + (uint32_t)cur * STAGE_BYTES;
#pragma unroll
        for (int j = 0; j < 4; j++) {
            uint32_t cb0 = (uint32_t)(j * 32 + tig * 4);
            uint32_t cb1 = cb0 + 16;

            uint32_t af[4][4];
#pragma unroll
            for (int i = 0; i < 4; i++) {
                uint32_t b0a = stg + aOff[i * 2 + 0], k0 = aKey[i * 2 + 0];
                uint32_t b1a = stg + aOff[i * 2 + 1], k1 = aKey[i * 2 + 1];
                af[i][0] = __float_as_uint(lds_f32(b0a + (cb0 ^ k0)));
                af[i][1] = __float_as_uint(lds_f32(b1a + (cb0 ^ k1)));
                af[i][2] = __float_as_uint(lds_f32(b0a + (cb1 ^ k0)));
                af[i][3] = __float_as_uint(lds_f32(b1a + (cb1 ^ k1)));
            }
            uint32_t bf[4][2];
#pragma unroll
            for (int nn = 0; nn < 4; nn++) {
                uint32_t ba = stg + bOff[nn], kk = bKey[nn];
                bf[nn][0] = __float_as_uint(lds_f32(ba + (cb0 ^ kk)));
                bf[nn][1] = __float_as_uint(lds_f32(ba + (cb1 ^ kk)));
            }
#pragma unroll
            for (int i = 0; i < 4; i++)
#pragma unroll
                for (int nn = 0; nn < 4; nn++)
                    mma_tf32(acc[i][nn], af[i][0], af[i][1], af[i][2], af[i][3],
                             bf[nn][0], bf[nn][1]);
        }

        cur = cur + 1 == STAGES ? 0 : cur + 1;
        nxs = nxs + 1 == STAGES ? 0 : nxs + 1;
    }

    // ---- epilogue: (gelu + tf32-round) -> direct STG.64, 32B-coalesced
    float* Cbase = C + (long)e * sCe + (long)mt * 128 * ldc + (long)nt * 128;
#pragma unroll
    for (int i = 0; i < 4; i++) {
        int r0 = wm * 64 + i * 16 + g;
#pragma unroll
        for (int nn = 0; nn < 4; nn++) {
            int col = wn * 32 + nn * 8 + 2 * tig;
            float v0 = acc[i][nn][0], v1 = acc[i][nn][1];
            float v2 = acc[i][nn][2], v3 = acc[i][nn][3];
            if (GELU) {
                v0 = tf32r(gelu_tanh(v0)); v1 = tf32r(gelu_tanh(v1));
                v2 = tf32r(gelu_tanh(v2)); v3 = tf32r(gelu_tanh(v3));
            }
            *(float2*)(Cbase + (long)r0 * ldc + col)       = make_float2(v0, v1);
            *(float2*)(Cbase + (long)(r0 + 8) * ldc + col) = make_float2(v2, v3);
        }
    }
}

// ---------------- launch ----------------
extern "C" void kernel_launch(void* const* d_in, const int* in_sizes, int n_in,
                              void* d_out, int out_size)
{
    const float* x  = (const float*)d_in[0];
    const float* w1 = (const float*)d_in[1];
    const float* w2 = (const float*)d_in[2];
    float* out = (float*)d_out;

    float *xr, *w1t, *w2t, *inter;
    cudaGetSymbolAddress((void**)&xr,    g_xr);
    cudaGetSymbolAddress((void**)&w1t,   g_w1t);
    cudaGetSymbolAddress((void**)&w2t,   g_w2t);
    cudaGetSymbolAddress((void**)&inter, g_inter);

    cudaFuncSetAttribute(gemm_mma_kernel<true>,
                         cudaFuncAttributeMaxDynamicSharedMemorySize, GEMM_SMEM);
    cudaFuncSetAttribute(gemm_mma_kernel<false>,
                         cudaFuncAttributeMaxDynamicSharedMemorySize, GEMM_SMEM);
    cudaFuncSetAttribute(gemm_mma_kernel<true>,
                         cudaFuncAttributePreferredSharedMemoryCarveout, 100);
    cudaFuncSetAttribute(gemm_mma_kernel<false>,
                         cudaFuncAttributePreferredSharedMemoryCarveout, 100);

    // 1) RNA-round X to tf32 grid
    {
        int n4 = T_ * H_ / 4;
        round_x_kernel<<<n4 / 256, 256>>>((const float4*)x, (float4*)xr, n4);
    }
    // 2) transpose + round weights: W1[E,H,F] -> [E,F,H]; W2[E,F,H] -> [E,H,F]
    transpose_rna_kernel<<<dim3(F_ / 32, H_ / 32, E_), dim3(32, 8)>>>(w1, w1t, H_, F_);
    transpose_rna_kernel<<<dim3(H_ / 32, F_ / 32, E_), dim3(32, 8)>>>(w2, w2t, F_, H_);

    // 3) GEMM1: inter = gelu(X @ W1)   (M=2048, N=4096, K=1024 per expert)
    gemm_mma_kernel<true><<<dim3(F_ / 128, TPE / 128, E_), 256, GEMM_SMEM>>>(
        xr, w1t, inter,
        H_, H_, F_,
        (long)TPE * H_, (long)F_ * H_, (long)TPE * F_,
        H_ / 32);

    // 4) GEMM2: out = inter @ W2       (M=2048, N=1024, K=4096 per expert)
    gemm_mma_kernel<false><<<dim3(H_ / 128, TPE / 128, E_), 256, GEMM_SMEM>>>(
        inter, w2t, out,
        F_, F_, H_,
        (long)TPE * F_, (long)H_ * F_, (long)TPE * H_,
        F_ / 32);
}

// round 6
// speedup vs baseline: 1.0143x; 1.0143x over previous
#include <cuda_runtime.h>
#include <cuda_bf16.h>
#include <cstdint>

// Problem constants
#define E_  8
#define H_  1024
#define F_  4096
#define T_  16384
#define TPE 2048   // tokens per expert

// ---------------- device scratch (static, allocation-free) ----------------
__device__ float g_xr  [(size_t)T_ * H_];        //  64 MB, RNA-rounded X
__device__ float g_w1t [(size_t)E_ * F_ * H_];   // 128 MB, W1^T per expert [E,F,H]
__device__ float g_w2t [(size_t)E_ * H_ * F_];   // 128 MB, W2^T per expert [E,H,F]
__device__ float g_inter[(size_t)E_ * TPE * F_]; // 256 MB, gelu(X@W1), tf32-rounded

// ---------------- helpers ----------------
__device__ __forceinline__ float tf32r(float x) {
    uint32_t u;
    asm("cvt.rna.tf32.f32 %0, %1;" : "=r"(u) : "f"(x));
    return __uint_as_float(u);
}

#define SMEM_SWZ(off) ((off) ^ (((off) >> 3) & 0x70))

__device__ __forceinline__ void cp_async16(uint32_t sm, const void* g) {
    asm volatile("cp.async.cg.shared.global [%0], [%1], 16;" :: "r"(sm), "l"(g));
}
#define CP_COMMIT()   asm volatile("cp.async.commit_group;" ::: "memory")
#define CP_WAIT_1()   asm volatile("cp.async.wait_group 1;" ::: "memory")
#define CP_WAIT_0()   asm volatile("cp.async.wait_group 0;" ::: "memory")

__device__ __forceinline__ uint32_t smem_u32(const void* p) {
    uint32_t a;
    asm("{ .reg .u64 t; cvta.to.shared.u64 t, %1; cvt.u32.u64 %0, t; }" : "=r"(a) : "l"(p));
    return a;
}

__device__ __forceinline__ float lds_f32(uint32_t addr) {
    float v;
    asm volatile("ld.shared.f32 %0, [%1];" : "=f"(v) : "r"(addr));
    return v;
}

// mma.sync m16n8k8 tf32 (portable PTX, lowers to legacy HMMA on sm_103)
__device__ __forceinline__ void mma_tf32(float* d,
                                         uint32_t a0, uint32_t a1, uint32_t a2, uint32_t a3,
                                         uint32_t b0, uint32_t b1) {
    asm volatile(
        "mma.sync.aligned.m16n8k8.row.col.f32.tf32.tf32.f32 "
        "{%0,%1,%2,%3}, {%4,%5,%6,%7}, {%8,%9}, {%0,%1,%2,%3};"
        : "+f"(d[0]), "+f"(d[1]), "+f"(d[2]), "+f"(d[3])
        : "r"(a0), "r"(a1), "r"(a2), "r"(a3), "r"(b0), "r"(b1));
}

__device__ __forceinline__ float gelu_tanh(float x) {
    float u = 0.7978845608028654f * (x + 0.044715f * x * x * x);
    float au = fabsf(u);
    float e = __expf(-2.0f * au);
    float t = (1.0f - e) * __frcp_rn(1.0f + e);
    t = copysignf(t, u);
    return 0.5f * x * (1.0f + t);
}

// ---------------- prep kernels ----------------
__global__ void round_x_kernel(const float4* __restrict__ x, float4* __restrict__ o, int n4) {
    int i = blockIdx.x * blockDim.x + threadIdx.x;
    if (i < n4) {
        float4 v = x[i];
        v.x = tf32r(v.x); v.y = tf32r(v.y); v.z = tf32r(v.z); v.w = tf32r(v.w);
        o[i] = v;
    }
}

// W [E][R][C] -> WT [E][C][R], fused RNA rounding. block (32,8), grid (C/32, R/32, E)
__global__ void transpose_rna_kernel(const float* __restrict__ W, float* __restrict__ WT,
                                     int R, int C) {
    __shared__ float t[32][33];
    int e = blockIdx.z;
    const float* Wb = W + (size_t)e * R * C;
    float* Tb = WT + (size_t)e * R * C;
    int c0 = blockIdx.x * 32, r0 = blockIdx.y * 32;
    int tx = threadIdx.x, ty = threadIdx.y;
#pragma unroll
    for (int i = 0; i < 32; i += 8)
        t[ty + i][tx] = tf32r(Wb[(size_t)(r0 + ty + i) * C + c0 + tx]);
    __syncthreads();
#pragma unroll
    for (int i = 0; i < 32; i += 8)
        Tb[(size_t)(c0 + ty + i) * R + r0 + tx] = t[tx][ty + i];
}

// ---------------- mma.sync tf32 GEMM: C[M,N] = A(K-major) . B(K-major)^T ----------------
// CTA tile 128x128, 128 threads, warp grid 2(m) x 2(n), warp tile 64x64
// (m_atoms=4, n_atoms=8). Cuts smem bytes/MMA from 192B to 128B vs the 2x4
// grid -> crossbar no longer the binder. 3 stages x 32KB = 96KB, 2 CTAs/SM.
#define STAGES      3
#define STAGE_BYTES 32768            // 16KB A + 16KB B per 32-K slab
#define GEMM_SMEM   (STAGES * STAGE_BYTES)

template <bool GELU>
__global__ __launch_bounds__(128, 2) void gemm_mma_kernel(
    const float* __restrict__ A, const float* __restrict__ B, float* __restrict__ C,
    int lda, int ldb, int ldc,
    long sAe, long sBe, long sCe, int KT)
{
    extern __shared__ char smem[];
    uint32_t sb = smem_u32(smem);
    int tid = threadIdx.x;
    int lane = tid & 31, wid = tid >> 5;
    int g = lane >> 2, tig = lane & 3;
    int wm = wid & 1, wn = wid >> 1;
    int nt = blockIdx.x, mt = blockIdx.y, e = blockIdx.z;

    const float* Abase = A + (long)e * sAe + (long)mt * 128 * lda;
    const float* Bbase = B + (long)e * sBe + (long)nt * 128 * ldb;

    // per-stage loader: 128 rows x 128B per operand, SW128 swizzle, 16B chunks
    auto load_stage = [&](int stg, int kt) {
        uint32_t sA = sb + stg * STAGE_BYTES;
        uint32_t sB = sA + 16384;
        const float* ga = Abase + kt * 32;
        const float* gb = Bbase + kt * 32;
#pragma unroll
        for (int i = 0; i < 8; i++) {
            int id = tid + i * 128;
            int row = id >> 3;
            int c = (id & 7) * 16;
            cp_async16(sA + SMEM_SWZ(row * 128 + c), (const char*)(ga + (long)row * lda) + c);
        }
#pragma unroll
        for (int i = 0; i < 8; i++) {
            int id = tid + i * 128;
            int row = id >> 3;
            int c = (id & 7) * 16;
            cp_async16(sB + SMEM_SWZ(row * 128 + c), (const char*)(gb + (long)row * ldb) + c);
        }
    };

    // fragment row base offsets. All fragment rows are == g (mod 8), so the
    // SW128 XOR key is the single constant (g<<4).
    uint32_t key = (uint32_t)(g << 4);
    uint32_t aOff[4][2];   // [m-atom][half]: rows wm*64 + i*16 + h*8 + g
#pragma unroll
    for (int i = 0; i < 4; i++)
#pragma unroll
        for (int h = 0; h < 2; h++)
            aOff[i][h] = (uint32_t)((wm * 64 + i * 16 + h * 8 + g) * 128);
    uint32_t bOff[8];      // [n-atom]: rows wn*64 + nn*8 + g
#pragma unroll
    for (int nn = 0; nn < 8; nn++)
        bOff[nn] = (uint32_t)(16384 + (wn * 64 + nn * 8 + g) * 128);

    float acc[4][8][4];
#pragma unroll
    for (int i = 0; i < 4; i++)
#pragma unroll
        for (int nn = 0; nn < 8; nn++)
#pragma unroll
            for (int r = 0; r < 4; r++) acc[i][nn][r] = 0.0f;

    // prologue: 2 slabs in flight
    load_stage(0, 0); CP_COMMIT();
    load_stage(1, 1); CP_COMMIT();

    int cur = 0, nxs = 2;
    for (int kt = 0; kt < KT; kt++) {
        if (kt < KT - 1) { CP_WAIT_1(); } else { CP_WAIT_0(); }
        // single barrier: proves slab kt resident AND buffer `nxs` fully consumed
        __syncthreads();

        int nx = kt + 2;
        if (nx < KT) {
            load_stage(nxs, nx);
            CP_COMMIT();
        }

        uint32_t stg = sb + (uint32_t)cur * STAGE_BYTES;
#pragma unroll
        for (int j = 0; j < 4; j++) {
            uint32_t cb0 = (uint32_t)(j * 32 + tig * 4) ^ key;
            uint32_t cb1 = (uint32_t)(j * 32 + tig * 4 + 16) ^ key;

            uint32_t af[4][4];
#pragma unroll
            for (int i = 0; i < 4; i++) {
                af[i][0] = __float_as_uint(lds_f32(stg + aOff[i][0] + cb0));
                af[i][1] = __float_as_uint(lds_f32(stg + aOff[i][1] + cb0));
                af[i][2] = __float_as_uint(lds_f32(stg + aOff[i][0] + cb1));
                af[i][3] = __float_as_uint(lds_f32(stg + aOff[i][1] + cb1));
            }
            uint32_t bf[8][2];
#pragma unroll
            for (int nn = 0; nn < 8; nn++) {
                bf[nn][0] = __float_as_uint(lds_f32(stg + bOff[nn] + cb0));
                bf[nn][1] = __float_as_uint(lds_f32(stg + bOff[nn] + cb1));
            }
#pragma unroll
            for (int i = 0; i < 4; i++)
#pragma unroll
                for (int nn = 0; nn < 8; nn++)
                    mma_tf32(acc[i][nn], af[i][0], af[i][1], af[i][2], af[i][3],
                             bf[nn][0], bf[nn][1]);
        }

        cur = cur + 1 == STAGES ? 0 : cur + 1;
        nxs = nxs + 1 == STAGES ? 0 : nxs + 1;
    }

    // ---- epilogue: (gelu + tf32-round) -> direct STG.64, 32B-coalesced
    float* Cbase = C + (long)e * sCe + (long)mt * 128 * ldc + (long)nt * 128;
#pragma unroll
    for (int i = 0; i < 4; i++) {
        int r0 = wm * 64 + i * 16 + g;
#pragma unroll
        for (int nn = 0; nn < 8; nn++) {
            int col = wn * 64 + nn * 8 + 2 * tig;
            float v0 = acc[i][nn][0], v1 = acc[i][nn][1];
            float v2 = acc[i][nn][2], v3 = acc[i][nn][3];
            if (GELU) {
                v0 = tf32r(gelu_tanh(v0)); v1 = tf32r(gelu_tanh(v1));
                v2 = tf32r(gelu_tanh(v2)); v3 = tf32r(gelu_tanh(v3));
            }
            *(float2*)(Cbase + (long)r0 * ldc + col)       = make_float2(v0, v1);
            *(float2*)(Cbase + (long)(r0 + 8) * ldc + col) = make_float2(v2, v3);
        }
    }
}

// ---------------- launch ----------------
extern "C" void kernel_launch(void* const* d_in, const int* in_sizes, int n_in,
                              void* d_out, int out_size)
{
    const float* x  = (const float*)d_in[0];
    const float* w1 = (const float*)d_in[1];
    const float* w2 = (const float*)d_in[2];
    float* out = (float*)d_out;

    float *xr, *w1t, *w2t, *inter;
    cudaGetSymbolAddress((void**)&xr,    g_xr);
    cudaGetSymbolAddress((void**)&w1t,   g_w1t);
    cudaGetSymbolAddress((void**)&w2t,   g_w2t);
    cudaGetSymbolAddress((void**)&inter, g_inter);

    cudaFuncSetAttribute(gemm_mma_kernel<true>,
                         cudaFuncAttributeMaxDynamicSharedMemorySize, GEMM_SMEM);
    cudaFuncSetAttribute(gemm_mma_kernel<false>,
                         cudaFuncAttributeMaxDynamicSharedMemorySize, GEMM_SMEM);
    cudaFuncSetAttribute(gemm_mma_kernel<true>,
                         cudaFuncAttributePreferredSharedMemoryCarveout, 100);
    cudaFuncSetAttribute(gemm_mma_kernel<false>,
                         cudaFuncAttributePreferredSharedMemoryCarveout, 100);

    // 1) RNA-round X to tf32 grid
    {
        int n4 = T_ * H_ / 4;
        round_x_kernel<<<n4 / 256, 256>>>((const float4*)x, (float4*)xr, n4);
    }
    // 2) transpose + round weights: W1[E,H,F] -> [E,F,H]; W2[E,F,H] -> [E,H,F]
    transpose_rna_kernel<<<dim3(F_ / 32, H_ / 32, E_), dim3(32, 8)>>>(w1, w1t, H_, F_);
    transpose_rna_kernel<<<dim3(H_ / 32, F_ / 32, E_), dim3(32, 8)>>>(w2, w2t, F_, H_);

    // 3) GEMM1: inter = gelu(X @ W1)   (M=2048, N=4096, K=1024 per expert)
    gemm_mma_kernel<true><<<dim3(F_ / 128, TPE / 128, E_), 128, GEMM_SMEM>>>(
        xr, w1t, inter,
        H_, H_, F_,
        (long)TPE * H_, (long)F_ * H_, (long)TPE * F_,
        H_ / 32);

    // 4) GEMM2: out = inter @ W2       (M=2048, N=1024, K=4096 per expert)
    gemm_mma_kernel<false><<<dim3(H_ / 128, TPE / 128, E_), 128, GEMM_SMEM>>>(
        inter, w2t, out,
        F_, F_, H_,
        (long)TPE * F_, (long)H_ * F_, (long)TPE * H_,
        F_ / 32);
}